// round 9
// baseline (speedup 1.0000x reference)
#include <cuda_runtime.h>
#include <cuda_fp16.h>
#include <math.h>
#include <stdint.h>

// ---------------- problem constants ----------------
#define BATCH   8
#define CH      256
#define HH      64
#define WW      64
#define HWSZ    (HH*WW)          // 4096
#define NTOK    (BATCH*HWSZ)     // 32768
#define HID     1024
#define NHEAD   8
#define HDIM    32
#define CP2     (CH/2)           // 128 channel pairs

// ---------------- scratch ----------------
__device__ __half  g_ts[NTOK*CH];        // sub transposed [tok][c]
__device__ __half  g_to[NTOK*CH];        // ori transposed [tok][c]
__device__ __half2 g_q [BATCH*CP2*HWSZ]; // channel-pair-major
__device__ __half2 g_k [BATCH*CP2*HWSZ];
__device__ __half2 g_v [BATCH*CP2*HWSZ];
__device__ __half2 g_x [NTOK*CP2];       // attention out, [tok][c] pairs
__device__ float   g_xp[NTOK*CH];        // proj out fp32 (residual/LN in)
__device__ __half  g_ln[NTOK*CH];        // layernorm out
__device__ __half  g_h [NTOK*HID];       // mlp hidden
__device__ __half  g_wq [CH*CH];         // fp16 weights
__device__ __half  g_wkv[2*CH*CH];       // wk rows 0..255 | wv rows 256..511
__device__ __half  g_wp [CH*CH];
__device__ __half  g_w1 [HID*CH];
__device__ __half  g_w2 [CH*HID];

// ---------------- helpers ----------------
__device__ __forceinline__ uint32_t smem_u32(const void* p) {
    uint32_t a;
    asm("{ .reg .u64 t; cvta.to.shared.u64 t, %1; cvt.u32.u64 %0, t; }"
        : "=r"(a) : "l"(p));
    return a;
}
__device__ __forceinline__ void cp16(uint32_t s, const void* g) {
    asm volatile("cp.async.cg.shared.global [%0], [%1], 16;" :: "r"(s), "l"(g));
}
#define CP_COMMIT() asm volatile("cp.async.commit_group;" ::: "memory")
#define CP_WAIT2()  asm volatile("cp.async.wait_group 2;" ::: "memory")

__device__ __forceinline__ void ldsm_x4(uint32_t r[4], uint32_t addr) {
    asm volatile("ldmatrix.sync.aligned.m8n8.x4.shared.b16 {%0,%1,%2,%3}, [%4];"
        : "=r"(r[0]), "=r"(r[1]), "=r"(r[2]), "=r"(r[3]) : "r"(addr));
}
__device__ __forceinline__ void mma_f16(float c[4], const uint32_t a[4],
                                        uint32_t b0, uint32_t b1) {
    asm volatile(
        "mma.sync.aligned.m16n8k16.row.col.f32.f16.f16.f32 "
        "{%0,%1,%2,%3}, {%4,%5,%6,%7}, {%8,%9}, {%0,%1,%2,%3};\n"
        : "+f"(c[0]), "+f"(c[1]), "+f"(c[2]), "+f"(c[3])
        : "r"(a[0]), "r"(a[1]), "r"(a[2]), "r"(a[3]), "r"(b0), "r"(b1));
}

// =====================================================================
// fp16 NT GEMM: C[m,n] = sum_k A[m,k] * W[n,k] + epilogue
// CTA 128x128, 128 threads (4 warps, warp tile 64x64 in a 2x2 grid),
// K-chunk 64, 3-stage cp.async, ldmatrix, swizzled 128B smem rows.
// Per k16 step: 8 LDSM + 32 HMMA per warp (mma:ldsm = 4.0).
// MODE 4: qkv single -> half2 channel-pair transposed store (out1)
// MODE 5: kv stacked -> n<256: out1 (k), n>=256: aux (v)
// MODE 0: proj -> +bias, fp32 store [m][CH]
// MODE 1: fc1  -> +bias, exact GELU, half store [m][HID]
// MODE 2: fc2  -> +bias +resid fp32 (aux), transposed fp32 store [B][C][H][W]
// =====================================================================
#define STAGE_B 32768   // 16KB A + 16KB B
#define SMEM_SZ (3*STAGE_B)

template<int MODE, int KDIM>
__global__ __launch_bounds__(128, 2)
void gemm_h(const __half* __restrict__ A, const __half* __restrict__ Wt,
            const float* __restrict__ bias, void* __restrict__ out1,
            void* __restrict__ aux)
{
    extern __shared__ __align__(128) char smem[];
    const uint32_t sb = smem_u32(smem);

    const int tid  = threadIdx.x;
    const int lane = tid & 31;
    const int wid  = tid >> 5;       // 0..3
    const int wm   = wid & 1;        // m: 64-row block
    const int wn   = wid >> 1;       // n: 64-col block
    const int lq   = lane >> 2;
    const int lr   = lane & 3;

    const int nT = blockIdx.x * 128;
    const int mT = blockIdx.y * 128;
    const int NCH = KDIM / 64;

    // ldmatrix row bases (per 16-row tile, proven pattern)
    const int l15   = lane & 15;
    const int qsel  = lane >> 4;     // selects k8 half within q-pair
    const int arow0 = wm * 64 + l15;
    const int brow0 = wn * 64 + l15;
    const int xorA  = arow0 & 7;     // (row+16k) & 7 == row & 7

    float acc[4][8][4];
    #pragma unroll
    for (int i = 0; i < 4; i++)
        #pragma unroll
        for (int j = 0; j < 8; j++)
            #pragma unroll
            for (int u = 0; u < 4; u++) acc[i][j][u] = 0.f;

    auto load_stage = [&](int s, int kt) {
        const uint32_t ab = sb + s * STAGE_B;
        const uint32_t bbm = ab + 16384;
        #pragma unroll
        for (int j = 0; j < 8; j++) {
            int c = tid + j * 128;          // 0..1023
            int row = c >> 3, q = c & 7;
            uint32_t off = (uint32_t)row * 128 + (uint32_t)((q ^ (row & 7)) * 16);
            cp16(ab  + off, A  + (size_t)(mT + row) * KDIM + kt + q * 8);
            cp16(bbm + off, Wt + (size_t)(nT + row) * KDIM + kt + q * 8);
        }
    };

    load_stage(0, 0);  CP_COMMIT();
    if (NCH > 1) load_stage(1, 64);
    CP_COMMIT();
    if (NCH > 2) load_stage(2, 128);
    CP_COMMIT();

    for (int it = 0; it < NCH; it++) {
        const int s = it % 3;
        CP_WAIT2();
        __syncthreads();

        const uint32_t ab = sb + s * STAGE_B;
        const uint32_t bbm = ab + 16384;

        #pragma unroll
        for (int ks = 0; ks < 4; ks++) {
            const int qa = ks * 2 + qsel;
            const uint32_t qoff = (uint32_t)((qa ^ xorA) * 16);
            uint32_t af[4][4], bf[4][4];
            #pragma unroll
            for (int mt = 0; mt < 4; mt++)
                ldsm_x4(af[mt], ab + (uint32_t)(arow0 + mt * 16) * 128 + qoff);
            #pragma unroll
            for (int nt = 0; nt < 4; nt++)
                ldsm_x4(bf[nt], bbm + (uint32_t)(brow0 + nt * 16) * 128 + qoff);
            #pragma unroll
            for (int mt = 0; mt < 4; mt++)
                #pragma unroll
                for (int nt = 0; nt < 4; nt++) {
                    mma_f16(acc[mt][nt*2  ], af[mt], bf[nt][0], bf[nt][2]);
                    mma_f16(acc[mt][nt*2+1], af[mt], bf[nt][1], bf[nt][3]);
                }
        }
        __syncthreads();
        if (it + 3 < NCH) load_stage(s, (it + 3) * 64);
        CP_COMMIT();
    }

    // ---------------- epilogue ----------------
    #pragma unroll
    for (int mt = 0; mt < 4; mt++) {
        #pragma unroll
        for (int idx = 0; idx < 8; idx++) {
            const int nt2 = idx >> 1, tt = idx & 1;
            const int m0 = mT + wm * 64 + mt * 16 + lq;
            const int n0 = nT + wn * 64 + nt2 * 16 + tt * 8 + (lr << 1);
            const float* cc = acc[mt][idx];

            if (MODE == 4 || MODE == 5) {
                const int bi = m0 >> 12;
                const int hw = m0 & 4095;
                __half2* dst;
                int ch;
                if (MODE == 5) {
                    dst = (n0 < CH) ? (__half2*)out1 : (__half2*)aux;
                    ch = n0 & (CH - 1);
                } else { dst = (__half2*)out1; ch = n0; }
                __half2* p = dst + (size_t)bi * CP2 * HWSZ + (size_t)(ch >> 1) * HWSZ;
                p[hw    ] = __floats2half2_rn(cc[0], cc[1]);
                p[hw + 8] = __floats2half2_rn(cc[2], cc[3]);
            } else if (MODE == 0) {
                float* o = (float*)out1;
                float2 bv = *(const float2*)&bias[n0];
                *(float2*)&o[(size_t)m0 * CH + n0] =
                    make_float2(cc[0] + bv.x, cc[1] + bv.y);
                *(float2*)&o[(size_t)(m0 + 8) * CH + n0] =
                    make_float2(cc[2] + bv.x, cc[3] + bv.y);
            } else if (MODE == 1) {
                __half* o = (__half*)out1;
                float2 bv = *(const float2*)&bias[n0];
                float v[4] = {cc[0] + bv.x, cc[1] + bv.y, cc[2] + bv.x, cc[3] + bv.y};
                #pragma unroll
                for (int u = 0; u < 4; u++)
                    v[u] = 0.5f * v[u] * (1.f + erff(v[u] * 0.70710678118654752f));
                *(__half2*)&o[(size_t)m0 * HID + n0]       = __floats2half2_rn(v[0], v[1]);
                *(__half2*)&o[(size_t)(m0 + 8) * HID + n0] = __floats2half2_rn(v[2], v[3]);
            } else {
                float* o = (float*)out1;
                const float* resid = (const float*)aux;
                float2 bv = *(const float2*)&bias[n0];
                float2 r0 = *(const float2*)&resid[(size_t)m0 * CH + n0];
                float2 r1 = *(const float2*)&resid[(size_t)(m0 + 8) * CH + n0];
                const int bi = m0 >> 12;
                const int hw = m0 & 4095;
                float* p = o + (size_t)bi * CH * HWSZ;
                p[(size_t)(n0    ) * HWSZ + hw    ] = cc[0] + bv.x + r0.x;
                p[(size_t)(n0 + 1) * HWSZ + hw    ] = cc[1] + bv.y + r0.y;
                p[(size_t)(n0    ) * HWSZ + hw + 8] = cc[2] + bv.x + r1.x;
                p[(size_t)(n0 + 1) * HWSZ + hw + 8] = cc[3] + bv.y + r1.y;
            }
        }
    }
}

// =====================================================================
// Tiled transpose + fp16 cvt: [b][256][4096] fp32 -> [b*4096][256] fp16
// =====================================================================
__global__ void transpose_h(const float* __restrict__ in, __half* __restrict__ out)
{
    __shared__ float t[32][33];
    const int b  = blockIdx.z;
    const int p0 = blockIdx.x * 32;
    const int c0 = blockIdx.y * 32;
    const int tx = threadIdx.x, ty = threadIdx.y;   // 32 x 8
    const float* ib = in + (size_t)b * CH * HWSZ;
    __half* ob = out + (size_t)b * HWSZ * CH;
    #pragma unroll
    for (int i = 0; i < 4; i++)
        t[ty + 8*i][tx] = ib[(size_t)(c0 + ty + 8*i) * HWSZ + p0 + tx];
    __syncthreads();
    #pragma unroll
    for (int i = 0; i < 4; i++)
        ob[(size_t)(p0 + ty + 8*i) * CH + c0 + tx] = __float2half_rn(t[tx][ty + 8*i]);
}

// =====================================================================
// Dilated 3x3 local attention, branchless gathers (clamped idx + mask).
// =====================================================================
__global__ __launch_bounds__(128)
void attn_kernel(const __half2* __restrict__ q,
                 const __half2* __restrict__ k,
                 const __half2* __restrict__ v,
                 __half2* __restrict__ xo)
{
    const int b    = blockIdx.z;
    const int head = blockIdx.y;
    const int n    = blockIdx.x * 128 + threadIdx.x;
    const int py   = n >> 6;
    const int px   = n & 63;
    const int dil  = (head >> 1) + 1;

    const size_t base = ((size_t)b * CP2 + head * (HDIM/2)) * HWSZ;
    const __half2* qb = q + base + n;
    const __half2* kb = k + base;
    const __half2* vb = v + base;

    float2 qr[16];
    #pragma unroll
    for (int cp = 0; cp < 16; cp++) qr[cp] = __half22float2(qb[(size_t)cp * HWSZ]);

    int nn[9];
    float msk[9];
    #pragma unroll
    for (int t = 0; t < 9; t++) {
        int yy = py + (t / 3 - 1) * dil;
        int xx = px + (t % 3 - 1) * dil;
        const bool in = (yy >= 0 && yy < HH && xx >= 0 && xx < WW);
        nn[t] = in ? (yy * WW + xx) : n;
        msk[t] = in ? 1.f : 0.f;
    }

    float logit[9];
    #pragma unroll
    for (int t = 0; t < 9; t++) {
        float acc = 0.f;
        #pragma unroll
        for (int cp = 0; cp < 16; cp++) {
            float2 kv = __half22float2(kb[(size_t)cp * HWSZ + nn[t]]);
            acc += qr[cp].x * kv.x + qr[cp].y * kv.y;
        }
        logit[t] = acc * msk[t] * 0.17677669529663687f;
    }

    float mx = logit[0];
    #pragma unroll
    for (int t = 1; t < 9; t++) mx = fmaxf(mx, logit[t]);
    float s = 0.f;
    #pragma unroll
    for (int t = 0; t < 9; t++) { logit[t] = __expf(logit[t] - mx); s += logit[t]; }
    const float inv = 1.f / s;
    #pragma unroll
    for (int t = 0; t < 9; t++) logit[t] *= inv * msk[t];

    __half2* xrow = xo + (size_t)(b * HWSZ + n) * CP2 + head * (HDIM/2);
    #pragma unroll
    for (int cp = 0; cp < 16; cp++) {
        float ox = 0.f, oy = 0.f;
        #pragma unroll
        for (int t = 0; t < 9; t++) {
            float2 vv = __half22float2(vb[(size_t)cp * HWSZ + nn[t]]);
            ox += logit[t] * vv.x;
            oy += logit[t] * vv.y;
        }
        xrow[cp] = __floats2half2_rn(ox, oy);
    }
}

// =====================================================================
// LayerNorm over 256 channels: fp32 in (g_xp), fp16 out (g_ln).
// =====================================================================
__global__ void ln_kernel(const float* __restrict__ xp,
                          const float* __restrict__ w,
                          const float* __restrict__ bb,
                          __half2* __restrict__ out)
{
    const int warp = threadIdx.x >> 5;
    const int lane = threadIdx.x & 31;
    const int tok  = blockIdx.x * 8 + warp;
    const float* row = xp + (size_t)tok * CH;

    float4 v0 = *(const float4*)&row[lane * 8];
    float4 v1 = *(const float4*)&row[lane * 8 + 4];
    float va[8] = {v0.x, v0.y, v0.z, v0.w, v1.x, v1.y, v1.z, v1.w};

    float s = 0.f, sq = 0.f;
    #pragma unroll
    for (int u = 0; u < 8; u++) { s += va[u]; sq += va[u] * va[u]; }
    #pragma unroll
    for (int o = 16; o; o >>= 1) {
        s  += __shfl_xor_sync(0xffffffffu, s,  o);
        sq += __shfl_xor_sync(0xffffffffu, sq, o);
    }
    const float mean = s * (1.f / 256.f);
    const float var  = sq * (1.f / 256.f) - mean * mean;
    const float inv  = rsqrtf(var + 1e-5f);

    __half2* orow = out + (size_t)tok * CP2 + lane * 4;
    #pragma unroll
    for (int j = 0; j < 4; j++) {
        int ch = lane * 8 + j * 2;
        float a0 = (va[j*2]   - mean) * inv * w[ch]     + bb[ch];
        float a1 = (va[j*2+1] - mean) * inv * w[ch + 1] + bb[ch + 1];
        orow[j] = __floats2half2_rn(a0, a1);
    }
}

// =====================================================================
// Fused weight conversion: all six weights in one launch.
// =====================================================================
__global__ void cvt_all(const float* __restrict__ wq, const float* __restrict__ wk,
                        const float* __restrict__ wv, const float* __restrict__ wp,
                        const float* __restrict__ w1, const float* __restrict__ w2,
                        __half* __restrict__ owq, __half* __restrict__ owkv,
                        __half* __restrict__ owp, __half* __restrict__ ow1,
                        __half* __restrict__ ow2)
{
    const int i = blockIdx.x * 256 + threadIdx.x;
    const int S = CH * CH;          // 65536
    if      (i <     S) owq [i        ] = __float2half_rn(wq[i]);
    else if (i < 2 * S) owkv[i - S    ] = __float2half_rn(wk[i - S]);
    else if (i < 3 * S) owkv[i - S    ] = __float2half_rn(wv[i - 2*S]);
    else if (i < 4 * S) owp [i - 3*S  ] = __float2half_rn(wp[i - 3*S]);
    else if (i < 8 * S) ow1 [i - 4*S  ] = __float2half_rn(w1[i - 4*S]);
    else                ow2 [i - 8*S  ] = __float2half_rn(w2[i - 8*S]);
}

// =====================================================================
extern "C" void kernel_launch(void* const* d_in, const int* in_sizes, int n_in,
                              void* d_out, int out_size)
{
    const float* sub    = (const float*)d_in[0];
    const float* ori    = (const float*)d_in[1];
    const float* wq     = (const float*)d_in[2];
    const float* wk     = (const float*)d_in[3];
    const float* wv     = (const float*)d_in[4];
    const float* proj_w = (const float*)d_in[5];
    const float* proj_b = (const float*)d_in[6];
    const float* ln_w   = (const float*)d_in[7];
    const float* ln_b   = (const float*)d_in[8];
    const float* fc1_w  = (const float*)d_in[9];
    const float* fc1_b  = (const float*)d_in[10];
    const float* fc2_w  = (const float*)d_in[11];
    const float* fc2_b  = (const float*)d_in[12];
    float* out = (float*)d_out;

    __half *p_ts, *p_to, *p_ln, *p_h, *p_wq, *p_wkv, *p_wp, *p_w1, *p_w2;
    __half2 *p_q, *p_k, *p_v, *p_x;
    float *p_xp;
    cudaGetSymbolAddress((void**)&p_ts,  g_ts);
    cudaGetSymbolAddress((void**)&p_to,  g_to);
    cudaGetSymbolAddress((void**)&p_q,   g_q);
    cudaGetSymbolAddress((void**)&p_k,   g_k);
    cudaGetSymbolAddress((void**)&p_v,   g_v);
    cudaGetSymbolAddress((void**)&p_x,   g_x);
    cudaGetSymbolAddress((void**)&p_xp,  g_xp);
    cudaGetSymbolAddress((void**)&p_ln,  g_ln);
    cudaGetSymbolAddress((void**)&p_h,   g_h);
    cudaGetSymbolAddress((void**)&p_wq,  g_wq);
    cudaGetSymbolAddress((void**)&p_wkv, g_wkv);
    cudaGetSymbolAddress((void**)&p_wp,  g_wp);
    cudaGetSymbolAddress((void**)&p_w1,  g_w1);
    cudaGetSymbolAddress((void**)&p_w2,  g_w2);

    cudaFuncSetAttribute(gemm_h<4, CH >, cudaFuncAttributeMaxDynamicSharedMemorySize, SMEM_SZ);
    cudaFuncSetAttribute(gemm_h<5, CH >, cudaFuncAttributeMaxDynamicSharedMemorySize, SMEM_SZ);
    cudaFuncSetAttribute(gemm_h<0, CH >, cudaFuncAttributeMaxDynamicSharedMemorySize, SMEM_SZ);
    cudaFuncSetAttribute(gemm_h<1, CH >, cudaFuncAttributeMaxDynamicSharedMemorySize, SMEM_SZ);
    cudaFuncSetAttribute(gemm_h<2, HID>, cudaFuncAttributeMaxDynamicSharedMemorySize, SMEM_SZ);

    // 0: all weight conversions
    cvt_all<<<(12 * CH * CH) / 256, 256>>>(wq, wk, wv, proj_w, fc1_w, fc2_w,
                                           p_wq, p_wkv, p_wp, p_w1, p_w2);

    // 1,2: transpose inputs to [tok][c] fp16
    dim3 gt(HWSZ / 32, CH / 32, BATCH);
    dim3 bt(32, 8);
    transpose_h<<<gt, bt>>>(sub, p_ts);
    transpose_h<<<gt, bt>>>(ori, p_to);

    // 3: q GEMM   4: stacked k|v GEMM   5: attention
    dim3 gq(CH / 128, NTOK / 128);
    gemm_h<4, CH><<<gq, 128, SMEM_SZ>>>(p_ts, p_wq, nullptr, p_q, nullptr);
    dim3 gkv(2 * CH / 128, NTOK / 128);
    gemm_h<5, CH><<<gkv, 128, SMEM_SZ>>>(p_to, p_wkv, nullptr, p_k, p_v);
    dim3 ga(HWSZ / 128, NHEAD, BATCH);
    attn_kernel<<<ga, 128>>>(p_q, p_k, p_v, p_x);

    // proj + bias -> g_xp fp32
    dim3 gp(CH / 128, NTOK / 128);
    gemm_h<0, CH><<<gp, 128, SMEM_SZ>>>((const __half*)p_x, p_wp, proj_b, p_xp, nullptr);

    // layernorm -> g_ln fp16
    ln_kernel<<<NTOK / 8, 256>>>(p_xp, ln_w, ln_b, (__half2*)p_ln);

    // fc1 + bias + GELU -> g_h fp16
    dim3 g1(HID / 128, NTOK / 128);
    gemm_h<1, CH><<<g1, 128, SMEM_SZ>>>(p_ln, p_w1, fc1_b, p_h, nullptr);

    // fc2 + bias + residual, transposed fp32 store -> d_out [B][C][H][W]
    dim3 g2(CH / 128, NTOK / 128);
    gemm_h<2, HID><<<g2, 128, SMEM_SZ>>>(p_h, p_w2, fc2_b, out, p_xp);
}

// round 10
// speedup vs baseline: 1.0269x; 1.0269x over previous
#include <cuda_runtime.h>
#include <cuda_fp16.h>
#include <math.h>
#include <stdint.h>

// ---------------- problem constants ----------------
#define BATCH   8
#define CH      256
#define HH      64
#define WW      64
#define HWSZ    (HH*WW)          // 4096
#define NTOK    (BATCH*HWSZ)     // 32768
#define HID     1024
#define NHEAD   8
#define HDIM    32
#define CP2     (CH/2)           // 128 channel pairs

// ---------------- scratch ----------------
__device__ __half  g_ts[NTOK*CH];        // sub transposed [tok][c]
__device__ __half  g_to[NTOK*CH];        // ori transposed [tok][c]
__device__ __half2 g_q [BATCH*CP2*HWSZ]; // channel-pair-major
__device__ __half2 g_k [BATCH*CP2*HWSZ];
__device__ __half2 g_v [BATCH*CP2*HWSZ];
__device__ __half2 g_x [NTOK*CP2];       // attention out, [tok][c] pairs
__device__ float   g_xp[NTOK*CH];        // proj out fp32 (residual/LN in)
__device__ __half  g_ln[NTOK*CH];        // layernorm out
__device__ __half  g_h [NTOK*HID];       // mlp hidden
__device__ __half  g_wq [CH*CH];         // fp16 weights
__device__ __half  g_wkv[2*CH*CH];       // wk rows 0..255 | wv rows 256..511
__device__ __half  g_wp [CH*CH];
__device__ __half  g_w1 [HID*CH];
__device__ __half  g_w2 [CH*HID];

// ---------------- helpers ----------------
__device__ __forceinline__ uint32_t smem_u32(const void* p) {
    uint32_t a;
    asm("{ .reg .u64 t; cvta.to.shared.u64 t, %1; cvt.u32.u64 %0, t; }"
        : "=r"(a) : "l"(p));
    return a;
}
__device__ __forceinline__ void cp16(uint32_t s, const void* g) {
    asm volatile("cp.async.cg.shared.global [%0], [%1], 16;" :: "r"(s), "l"(g));
}
#define CP_COMMIT() asm volatile("cp.async.commit_group;" ::: "memory")
#define CP_WAIT2()  asm volatile("cp.async.wait_group 2;" ::: "memory")

__device__ __forceinline__ void ldsm_x4(uint32_t r[4], uint32_t addr) {
    asm volatile("ldmatrix.sync.aligned.m8n8.x4.shared.b16 {%0,%1,%2,%3}, [%4];"
        : "=r"(r[0]), "=r"(r[1]), "=r"(r[2]), "=r"(r[3]) : "r"(addr));
}
__device__ __forceinline__ void mma_f16(float c[4], const uint32_t a[4],
                                        uint32_t b0, uint32_t b1) {
    asm volatile(
        "mma.sync.aligned.m16n8k16.row.col.f32.f16.f16.f32 "
        "{%0,%1,%2,%3}, {%4,%5,%6,%7}, {%8,%9}, {%0,%1,%2,%3};\n"
        : "+f"(c[0]), "+f"(c[1]), "+f"(c[2]), "+f"(c[3])
        : "r"(a[0]), "r"(a[1]), "r"(a[2]), "r"(a[3]), "r"(b0), "r"(b1));
}

// =====================================================================
// fp16 NT GEMM (PROVEN round-8 config): CTA 128x128, 256 threads
// (8 warps, warp 32x64), K-chunk 64, 3-stage cp.async, ldmatrix.
// MODE 4: qkv single -> half2 channel-pair transposed store (out1)
// MODE 5: kv stacked -> n<256: out1 (k), n>=256: aux (v)
// MODE 0: proj -> +bias, fp32 store [m][CH]
// MODE 1: fc1  -> +bias, exact GELU, half store [m][HID]
// MODE 2: fc2  -> +bias +resid fp32 (aux), transposed fp32 store [B][C][H][W]
// =====================================================================
#define STAGE_B 32768   // 16KB A + 16KB B
#define SMEM_SZ (3*STAGE_B)

template<int MODE, int KDIM>
__global__ __launch_bounds__(256, 2)
void gemm_h(const __half* __restrict__ A, const __half* __restrict__ Wt,
            const float* __restrict__ bias, void* __restrict__ out1,
            void* __restrict__ aux)
{
    extern __shared__ __align__(128) char smem[];
    const uint32_t sb = smem_u32(smem);

    const int tid  = threadIdx.x;
    const int lane = tid & 31;
    const int wid  = tid >> 5;
    const int wm   = wid & 3;
    const int wn   = wid >> 2;
    const int lq   = lane >> 2;
    const int lr   = lane & 3;

    const int nT = blockIdx.x * 128;
    const int mT = blockIdx.y * 128;
    const int NCH = KDIM / 64;

    const int arow  = wm * 32 + (lane & 15);
    const int aqsel = lane >> 4;
    const uint32_t abase0 = (uint32_t)arow * 128;
    const uint32_t abase1 = (uint32_t)(arow + 16) * 128;
    const int axor = arow & 7;
    const int brow  = wn * 64 + (lane & 15);
    const int bqsel = lane >> 4;

    float acc[2][8][4];
    #pragma unroll
    for (int i = 0; i < 2; i++)
        #pragma unroll
        for (int j = 0; j < 8; j++)
            #pragma unroll
            for (int u = 0; u < 4; u++) acc[i][j][u] = 0.f;

    auto load_stage = [&](int s, int kt) {
        const uint32_t ab = sb + s * STAGE_B;
        const uint32_t bbm = ab + 16384;
        #pragma unroll
        for (int j = 0; j < 4; j++) {
            int c = tid + j * 256;
            int row = c >> 3, q = c & 7;
            uint32_t off = (uint32_t)row * 128 + (uint32_t)((q ^ (row & 7)) * 16);
            cp16(ab  + off, A  + (size_t)(mT + row) * KDIM + kt + q * 8);
            cp16(bbm + off, Wt + (size_t)(nT + row) * KDIM + kt + q * 8);
        }
    };

    load_stage(0, 0);  CP_COMMIT();
    if (NCH > 1) load_stage(1, 64);
    CP_COMMIT();
    if (NCH > 2) load_stage(2, 128);
    CP_COMMIT();

    for (int it = 0; it < NCH; it++) {
        const int s = it % 3;
        CP_WAIT2();
        __syncthreads();

        const uint32_t ab = sb + s * STAGE_B;
        const uint32_t bbm = ab + 16384;

        #pragma unroll
        for (int ks = 0; ks < 4; ks++) {
            const int q0 = ks * 2;
            uint32_t af[2][4];
            {
                const int qa = q0 + aqsel;
                ldsm_x4(af[0], ab + abase0 + (uint32_t)((qa ^ axor) * 16));
                ldsm_x4(af[1], ab + abase1 + (uint32_t)((qa ^ axor) * 16));
            }
            #pragma unroll
            for (int nt2 = 0; nt2 < 4; nt2++) {
                const int row = brow + nt2 * 16;
                const int qb = q0 + bqsel;
                uint32_t bf[4];
                ldsm_x4(bf, bbm + (uint32_t)row * 128 + (uint32_t)((qb ^ (row & 7)) * 16));
                mma_f16(acc[0][nt2*2  ], af[0], bf[0], bf[2]);
                mma_f16(acc[0][nt2*2+1], af[0], bf[1], bf[3]);
                mma_f16(acc[1][nt2*2  ], af[1], bf[0], bf[2]);
                mma_f16(acc[1][nt2*2+1], af[1], bf[1], bf[3]);
            }
        }
        __syncthreads();
        if (it + 3 < NCH) load_stage(s, (it + 3) * 64);
        CP_COMMIT();
    }

    // ---------------- epilogue ----------------
    #pragma unroll
    for (int mt = 0; mt < 2; mt++) {
        #pragma unroll
        for (int idx = 0; idx < 8; idx++) {
            const int nt2 = idx >> 1, tt = idx & 1;
            const int m0 = mT + wm * 32 + mt * 16 + lq;
            const int n0 = nT + wn * 64 + nt2 * 16 + tt * 8 + (lr << 1);
            const float* cc = acc[mt][idx];

            if (MODE == 4 || MODE == 5) {
                const int bi = m0 >> 12;
                const int hw = m0 & 4095;
                __half2* dst;
                int ch;
                if (MODE == 5) {
                    dst = (n0 < CH) ? (__half2*)out1 : (__half2*)aux;
                    ch = n0 & (CH - 1);
                } else { dst = (__half2*)out1; ch = n0; }
                __half2* p = dst + (size_t)bi * CP2 * HWSZ + (size_t)(ch >> 1) * HWSZ;
                p[hw    ] = __floats2half2_rn(cc[0], cc[1]);
                p[hw + 8] = __floats2half2_rn(cc[2], cc[3]);
            } else if (MODE == 0) {
                float* o = (float*)out1;
                float2 bv = *(const float2*)&bias[n0];
                *(float2*)&o[(size_t)m0 * CH + n0] =
                    make_float2(cc[0] + bv.x, cc[1] + bv.y);
                *(float2*)&o[(size_t)(m0 + 8) * CH + n0] =
                    make_float2(cc[2] + bv.x, cc[3] + bv.y);
            } else if (MODE == 1) {
                __half* o = (__half*)out1;
                float2 bv = *(const float2*)&bias[n0];
                float v[4] = {cc[0] + bv.x, cc[1] + bv.y, cc[2] + bv.x, cc[3] + bv.y};
                #pragma unroll
                for (int u = 0; u < 4; u++)
                    v[u] = 0.5f * v[u] * (1.f + erff(v[u] * 0.70710678118654752f));
                *(__half2*)&o[(size_t)m0 * HID + n0]       = __floats2half2_rn(v[0], v[1]);
                *(__half2*)&o[(size_t)(m0 + 8) * HID + n0] = __floats2half2_rn(v[2], v[3]);
            } else {
                float* o = (float*)out1;
                const float* resid = (const float*)aux;
                float2 bv = *(const float2*)&bias[n0];
                float2 r0 = *(const float2*)&resid[(size_t)m0 * CH + n0];
                float2 r1 = *(const float2*)&resid[(size_t)(m0 + 8) * CH + n0];
                const int bi = m0 >> 12;
                const int hw = m0 & 4095;
                float* p = o + (size_t)bi * CH * HWSZ;
                p[(size_t)(n0    ) * HWSZ + hw    ] = cc[0] + bv.x + r0.x;
                p[(size_t)(n0 + 1) * HWSZ + hw    ] = cc[1] + bv.y + r0.y;
                p[(size_t)(n0    ) * HWSZ + hw + 8] = cc[2] + bv.x + r1.x;
                p[(size_t)(n0 + 1) * HWSZ + hw + 8] = cc[3] + bv.y + r1.y;
            }
        }
    }
}

// =====================================================================
// Tiled transpose + fp16 cvt: [b][256][4096] fp32 -> [b*4096][256] fp16
// =====================================================================
__global__ void transpose_h(const float* __restrict__ in, __half* __restrict__ out)
{
    __shared__ float t[32][33];
    const int b  = blockIdx.z;
    const int p0 = blockIdx.x * 32;
    const int c0 = blockIdx.y * 32;
    const int tx = threadIdx.x, ty = threadIdx.y;   // 32 x 8
    const float* ib = in + (size_t)b * CH * HWSZ;
    __half* ob = out + (size_t)b * HWSZ * CH;
    #pragma unroll
    for (int i = 0; i < 4; i++)
        t[ty + 8*i][tx] = ib[(size_t)(c0 + ty + 8*i) * HWSZ + p0 + tx];
    __syncthreads();
    #pragma unroll
    for (int i = 0; i < 4; i++)
        ob[(size_t)(p0 + ty + 8*i) * CH + c0 + tx] = __float2half_rn(t[tx][ty + 8*i]);
}

// =====================================================================
// Dilated 3x3 local attention, SMEM-TILED k/v patches.
// Block = 128 pixels (2 image rows) x 1 head x 1 batch.
// Six k/v rows staged in smem (offsets {-d,1-d,0,1,d,1+d} from first row,
// clamped to [0,63] -> finite data; OOB taps masked exactly as before).
// All tap reads become conflict-free LDS. fp32 math throughout.
// =====================================================================
__global__ __launch_bounds__(128)
void attn_kernel(const __half2* __restrict__ q,
                 const __half2* __restrict__ k,
                 const __half2* __restrict__ v,
                 __half2* __restrict__ xo)
{
    __shared__ __align__(16) __half2 sk[6 * 16 * 64];   // [slot][cp][px] 24KB
    __shared__ __align__(16) __half2 sv[6 * 16 * 64];   // 24KB

    const int b    = blockIdx.z;
    const int head = blockIdx.y;
    const int tid  = threadIdx.x;
    const int n    = blockIdx.x * 128 + tid;
    const int r2   = blockIdx.x * 2;        // first of the 2 rows
    const int py   = n >> 6;
    const int px   = n & 63;
    const int pyl  = tid >> 6;              // 0/1: which of the 2 rows
    const int dil  = (head >> 1) + 1;

    const size_t base = ((size_t)b * CP2 + head * (HDIM/2)) * HWSZ;
    const __half2* kb = k + base;
    const __half2* vb = v + base;

    // slot j holds image row r2 + offs[j] (clamped)
    const int offs[6] = {-dil, 1 - dil, 0, 1, dil, 1 + dil};

    // stage k/v patches: 6 slots x 16 cp x 16 float4 (=64 half2 per row)
    for (int e = tid; e < 6 * 16 * 16; e += 128) {
        const int slot = e >> 8;            // /256
        const int rem  = e & 255;
        const int cp   = rem >> 4;
        const int g4   = rem & 15;
        int rowg = r2 + offs[slot];
        rowg = min(max(rowg, 0), HH - 1);
        const float4* srck = (const float4*)(kb + (size_t)cp * HWSZ + rowg * WW) + g4;
        const float4* srcv = (const float4*)(vb + (size_t)cp * HWSZ + rowg * WW) + g4;
        ((float4*)sk)[slot * 256 + cp * 16 + g4] = *srck;
        ((float4*)sv)[slot * 256 + cp * 16 + g4] = *srcv;
    }

    // q into registers (coalesced global)
    const __half2* qb = q + base + n;
    float2 qr[16];
    #pragma unroll
    for (int cp = 0; cp < 16; cp++) qr[cp] = __half22float2(qb[(size_t)cp * HWSZ]);

    __syncthreads();

    // per-tap smem base index + mask
    int sidx[9];
    float msk[9];
    #pragma unroll
    for (int t = 0; t < 9; t++) {
        const int dy = t / 3 - 1, dx = t % 3 - 1;
        const int yy = py + dy * dil;
        const int xx = px + dx * dil;
        const bool in = (yy >= 0 && yy < HH && xx >= 0 && xx < WW);
        msk[t] = in ? 1.f : 0.f;
        const int slot = (dy + 1) * 2 + pyl;
        const int xxc  = min(max(xx, 0), WW - 1);
        sidx[t] = slot * 1024 + xxc;        // + cp*64 in the loops
    }

    float logit[9];
    #pragma unroll
    for (int t = 0; t < 9; t++) {
        float acc = 0.f;
        #pragma unroll
        for (int cp = 0; cp < 16; cp++) {
            float2 kv = __half22float2(sk[sidx[t] + cp * 64]);
            acc += qr[cp].x * kv.x + qr[cp].y * kv.y;
        }
        logit[t] = acc * msk[t] * 0.17677669529663687f;
    }

    float mx = logit[0];
    #pragma unroll
    for (int t = 1; t < 9; t++) mx = fmaxf(mx, logit[t]);
    float s = 0.f;
    #pragma unroll
    for (int t = 0; t < 9; t++) { logit[t] = __expf(logit[t] - mx); s += logit[t]; }
    const float inv = 1.f / s;
    #pragma unroll
    for (int t = 0; t < 9; t++) logit[t] *= inv * msk[t];

    __half2* xrow = xo + (size_t)(b * HWSZ + n) * CP2 + head * (HDIM/2);
    #pragma unroll
    for (int cp = 0; cp < 16; cp++) {
        float ox = 0.f, oy = 0.f;
        #pragma unroll
        for (int t = 0; t < 9; t++) {
            float2 vv = __half22float2(sv[sidx[t] + cp * 64]);
            ox += logit[t] * vv.x;
            oy += logit[t] * vv.y;
        }
        xrow[cp] = __floats2half2_rn(ox, oy);
    }
}

// =====================================================================
// LayerNorm over 256 channels: fp32 in (g_xp), fp16 out (g_ln).
// =====================================================================
__global__ void ln_kernel(const float* __restrict__ xp,
                          const float* __restrict__ w,
                          const float* __restrict__ bb,
                          __half2* __restrict__ out)
{
    const int warp = threadIdx.x >> 5;
    const int lane = threadIdx.x & 31;
    const int tok  = blockIdx.x * 8 + warp;
    const float* row = xp + (size_t)tok * CH;

    float4 v0 = *(const float4*)&row[lane * 8];
    float4 v1 = *(const float4*)&row[lane * 8 + 4];
    float va[8] = {v0.x, v0.y, v0.z, v0.w, v1.x, v1.y, v1.z, v1.w};

    float s = 0.f, sq = 0.f;
    #pragma unroll
    for (int u = 0; u < 8; u++) { s += va[u]; sq += va[u] * va[u]; }
    #pragma unroll
    for (int o = 16; o; o >>= 1) {
        s  += __shfl_xor_sync(0xffffffffu, s,  o);
        sq += __shfl_xor_sync(0xffffffffu, sq, o);
    }
    const float mean = s * (1.f / 256.f);
    const float var  = sq * (1.f / 256.f) - mean * mean;
    const float inv  = rsqrtf(var + 1e-5f);

    __half2* orow = out + (size_t)tok * CP2 + lane * 4;
    #pragma unroll
    for (int j = 0; j < 4; j++) {
        int ch = lane * 8 + j * 2;
        float a0 = (va[j*2]   - mean) * inv * w[ch]     + bb[ch];
        float a1 = (va[j*2+1] - mean) * inv * w[ch + 1] + bb[ch + 1];
        orow[j] = __floats2half2_rn(a0, a1);
    }
}

// =====================================================================
// Fused weight conversion: all six weights in one launch.
// =====================================================================
__global__ void cvt_all(const float* __restrict__ wq, const float* __restrict__ wk,
                        const float* __restrict__ wv, const float* __restrict__ wp,
                        const float* __restrict__ w1, const float* __restrict__ w2,
                        __half* __restrict__ owq, __half* __restrict__ owkv,
                        __half* __restrict__ owp, __half* __restrict__ ow1,
                        __half* __restrict__ ow2)
{
    const int i = blockIdx.x * 256 + threadIdx.x;
    const int S = CH * CH;          // 65536
    if      (i <     S) owq [i        ] = __float2half_rn(wq[i]);
    else if (i < 2 * S) owkv[i - S    ] = __float2half_rn(wk[i - S]);
    else if (i < 3 * S) owkv[i - S    ] = __float2half_rn(wv[i - 2*S]);
    else if (i < 4 * S) owp [i - 3*S  ] = __float2half_rn(wp[i - 3*S]);
    else if (i < 8 * S) ow1 [i - 4*S  ] = __float2half_rn(w1[i - 4*S]);
    else                ow2 [i - 8*S  ] = __float2half_rn(w2[i - 8*S]);
}

// =====================================================================
extern "C" void kernel_launch(void* const* d_in, const int* in_sizes, int n_in,
                              void* d_out, int out_size)
{
    const float* sub    = (const float*)d_in[0];
    const float* ori    = (const float*)d_in[1];
    const float* wq     = (const float*)d_in[2];
    const float* wk     = (const float*)d_in[3];
    const float* wv     = (const float*)d_in[4];
    const float* proj_w = (const float*)d_in[5];
    const float* proj_b = (const float*)d_in[6];
    const float* ln_w   = (const float*)d_in[7];
    const float* ln_b   = (const float*)d_in[8];
    const float* fc1_w  = (const float*)d_in[9];
    const float* fc1_b  = (const float*)d_in[10];
    const float* fc2_w  = (const float*)d_in[11];
    const float* fc2_b  = (const float*)d_in[12];
    float* out = (float*)d_out;

    __half *p_ts, *p_to, *p_ln, *p_h, *p_wq, *p_wkv, *p_wp, *p_w1, *p_w2;
    __half2 *p_q, *p_k, *p_v, *p_x;
    float *p_xp;
    cudaGetSymbolAddress((void**)&p_ts,  g_ts);
    cudaGetSymbolAddress((void**)&p_to,  g_to);
    cudaGetSymbolAddress((void**)&p_q,   g_q);
    cudaGetSymbolAddress((void**)&p_k,   g_k);
    cudaGetSymbolAddress((void**)&p_v,   g_v);
    cudaGetSymbolAddress((void**)&p_x,   g_x);
    cudaGetSymbolAddress((void**)&p_xp,  g_xp);
    cudaGetSymbolAddress((void**)&p_ln,  g_ln);
    cudaGetSymbolAddress((void**)&p_h,   g_h);
    cudaGetSymbolAddress((void**)&p_wq,  g_wq);
    cudaGetSymbolAddress((void**)&p_wkv, g_wkv);
    cudaGetSymbolAddress((void**)&p_wp,  g_wp);
    cudaGetSymbolAddress((void**)&p_w1,  g_w1);
    cudaGetSymbolAddress((void**)&p_w2,  g_w2);

    cudaFuncSetAttribute(gemm_h<4, CH >, cudaFuncAttributeMaxDynamicSharedMemorySize, SMEM_SZ);
    cudaFuncSetAttribute(gemm_h<5, CH >, cudaFuncAttributeMaxDynamicSharedMemorySize, SMEM_SZ);
    cudaFuncSetAttribute(gemm_h<0, CH >, cudaFuncAttributeMaxDynamicSharedMemorySize, SMEM_SZ);
    cudaFuncSetAttribute(gemm_h<1, CH >, cudaFuncAttributeMaxDynamicSharedMemorySize, SMEM_SZ);
    cudaFuncSetAttribute(gemm_h<2, HID>, cudaFuncAttributeMaxDynamicSharedMemorySize, SMEM_SZ);

    // 0: all weight conversions
    cvt_all<<<(12 * CH * CH) / 256, 256>>>(wq, wk, wv, proj_w, fc1_w, fc2_w,
                                           p_wq, p_wkv, p_wp, p_w1, p_w2);

    // 1,2: transpose inputs to [tok][c] fp16
    dim3 gt(HWSZ / 32, CH / 32, BATCH);
    dim3 bt(32, 8);
    transpose_h<<<gt, bt>>>(sub, p_ts);
    transpose_h<<<gt, bt>>>(ori, p_to);

    // 3: q GEMM   4: stacked k|v GEMM   5: attention
    dim3 gq(CH / 128, NTOK / 128);
    gemm_h<4, CH><<<gq, 256, SMEM_SZ>>>(p_ts, p_wq, nullptr, p_q, nullptr);
    dim3 gkv(2 * CH / 128, NTOK / 128);
    gemm_h<5, CH><<<gkv, 256, SMEM_SZ>>>(p_to, p_wkv, nullptr, p_k, p_v);
    dim3 ga(HWSZ / 128, NHEAD, BATCH);
    attn_kernel<<<ga, 128>>>(p_q, p_k, p_v, p_x);

    // proj + bias -> g_xp fp32
    dim3 gp(CH / 128, NTOK / 128);
    gemm_h<0, CH><<<gp, 256, SMEM_SZ>>>((const __half*)p_x, p_wp, proj_b, p_xp, nullptr);

    // layernorm -> g_ln fp16
    ln_kernel<<<NTOK / 8, 256>>>(p_xp, ln_w, ln_b, (__half2*)p_ln);

    // fc1 + bias + GELU -> g_h fp16
    dim3 g1(HID / 128, NTOK / 128);
    gemm_h<1, CH><<<g1, 256, SMEM_SZ>>>(p_ln, p_w1, fc1_b, p_h, nullptr);

    // fc2 + bias + residual, transposed fp32 store -> d_out [B][C][H][W]
    dim3 g2(CH / 128, NTOK / 128);
    gemm_h<2, HID><<<g2, 256, SMEM_SZ>>>(p_h, p_w2, fc2_b, out, p_xp);
}

// round 11
// speedup vs baseline: 1.0615x; 1.0336x over previous
#include <cuda_runtime.h>
#include <cuda_fp16.h>
#include <math.h>
#include <stdint.h>

// ---------------- problem constants ----------------
#define BATCH   8
#define CH      256
#define HH      64
#define WW      64
#define HWSZ    (HH*WW)          // 4096
#define NTOK    (BATCH*HWSZ)     // 32768
#define HID     1024
#define NHEAD   8
#define HDIM    32
#define CP2     (CH/2)           // 128 channel pairs

// ---------------- scratch ----------------
__device__ __half  g_ts[NTOK*CH];        // sub transposed [tok][c]
__device__ __half  g_to[NTOK*CH];        // ori transposed [tok][c]
__device__ __half2 g_q [BATCH*CP2*HWSZ]; // channel-pair-major
__device__ __half2 g_k [BATCH*CP2*HWSZ];
__device__ __half2 g_v [BATCH*CP2*HWSZ];
__device__ __half2 g_x [NTOK*CP2];       // attention out, [tok][c] pairs
__device__ float   g_xp[NTOK*CH];        // proj out fp32 (residual/LN in)
__device__ __half  g_ln[NTOK*CH];        // layernorm out
__device__ __half  g_h [NTOK*HID];       // mlp hidden
__device__ __half  g_wq [CH*CH];         // fp16 weights
__device__ __half  g_wkv[2*CH*CH];       // wk rows 0..255 | wv rows 256..511
__device__ __half  g_wp [CH*CH];
__device__ __half  g_w1 [HID*CH];
__device__ __half  g_w2 [CH*HID];

// ---------------- helpers ----------------
__device__ __forceinline__ uint32_t smem_u32(const void* p) {
    uint32_t a;
    asm("{ .reg .u64 t; cvta.to.shared.u64 t, %1; cvt.u32.u64 %0, t; }"
        : "=r"(a) : "l"(p));
    return a;
}
__device__ __forceinline__ void cp16(uint32_t s, const void* g) {
    asm volatile("cp.async.cg.shared.global [%0], [%1], 16;" :: "r"(s), "l"(g));
}
#define CP_COMMIT() asm volatile("cp.async.commit_group;" ::: "memory")
#define CP_WAIT1()  asm volatile("cp.async.wait_group 1;" ::: "memory")

__device__ __forceinline__ void ldsm_x4(uint32_t r[4], uint32_t addr) {
    asm volatile("ldmatrix.sync.aligned.m8n8.x4.shared.b16 {%0,%1,%2,%3}, [%4];"
        : "=r"(r[0]), "=r"(r[1]), "=r"(r[2]), "=r"(r[3]) : "r"(addr));
}
__device__ __forceinline__ void mma_f16(float c[4], const uint32_t a[4],
                                        uint32_t b0, uint32_t b1) {
    asm volatile(
        "mma.sync.aligned.m16n8k16.row.col.f32.f16.f16.f32 "
        "{%0,%1,%2,%3}, {%4,%5,%6,%7}, {%8,%9}, {%0,%1,%2,%3};\n"
        : "+f"(c[0]), "+f"(c[1]), "+f"(c[2]), "+f"(c[3])
        : "r"(a[0]), "r"(a[1]), "r"(a[2]), "r"(a[3]), "r"(b0), "r"(b1));
}

// =====================================================================
// fp16 NT GEMM: CTA 128x128, 256 threads (8 warps, warp 32x64),
// K-chunk 64, 3-stage cp.async, SINGLE __syncthreads per K-chunk.
// MODE 6: combined qkv. bx<2: q = A(ts)*Wt(wq) -> out1.
//         bx>=2: kv = A2(to)*W2(wkv stacked) -> n<256: aux (k), else out2 (v)
//         (all half2 channel-pair transposed stores)
// MODE 0: proj -> +bias, fp32 store [m][CH]
// MODE 1: fc1  -> +bias, exact GELU, half store [m][HID]
// MODE 2: fc2  -> +bias +resid fp32 (aux), transposed fp32 store [B][C][H][W]
// =====================================================================
#define STAGE_B 32768   // 16KB A + 16KB B
#define SMEM_SZ (3*STAGE_B)

template<int MODE, int KDIM>
__global__ __launch_bounds__(256, 2)
void gemm_h(const __half* __restrict__ A, const __half* __restrict__ Wt,
            const float* __restrict__ bias, void* __restrict__ out1,
            void* __restrict__ aux,
            const __half* __restrict__ A2, const __half* __restrict__ W2,
            void* __restrict__ out2)
{
    extern __shared__ __align__(128) char smem[];
    const uint32_t sb = smem_u32(smem);

    const int tid  = threadIdx.x;
    const int lane = tid & 31;
    const int wid  = tid >> 5;
    const int wm   = wid & 3;
    const int wn   = wid >> 2;
    const int lq   = lane >> 2;
    const int lr   = lane & 3;

    // operand / tile selection
    const __half* Ap;
    const __half* Wp;
    int nT;
    bool isq = true;
    if (MODE == 6) {
        isq = (blockIdx.x < 2);
        if (isq) { Ap = A;  Wp = Wt; nT = blockIdx.x * 128; }
        else     { Ap = A2; Wp = W2; nT = (blockIdx.x - 2) * 128; }
    } else {
        Ap = A; Wp = Wt; nT = blockIdx.x * 128;
    }
    const int mT = blockIdx.y * 128;
    const int NCH = KDIM / 64;

    const int arow  = wm * 32 + (lane & 15);
    const int aqsel = lane >> 4;
    const uint32_t abase0 = (uint32_t)arow * 128;
    const uint32_t abase1 = (uint32_t)(arow + 16) * 128;
    const int axor = arow & 7;
    const int brow  = wn * 64 + (lane & 15);
    const int bqsel = lane >> 4;

    float acc[2][8][4];
    #pragma unroll
    for (int i = 0; i < 2; i++)
        #pragma unroll
        for (int j = 0; j < 8; j++)
            #pragma unroll
            for (int u = 0; u < 4; u++) acc[i][j][u] = 0.f;

    auto load_stage = [&](int s, int kt) {
        const uint32_t ab = sb + s * STAGE_B;
        const uint32_t bbm = ab + 16384;
        #pragma unroll
        for (int j = 0; j < 4; j++) {
            int c = tid + j * 256;
            int row = c >> 3, q = c & 7;
            uint32_t off = (uint32_t)row * 128 + (uint32_t)((q ^ (row & 7)) * 16);
            cp16(ab  + off, Ap + (size_t)(mT + row) * KDIM + kt + q * 8);
            cp16(bbm + off, Wp + (size_t)(nT + row) * KDIM + kt + q * 8);
        }
    };

    load_stage(0, 0);  CP_COMMIT();
    if (NCH > 1) load_stage(1, 64);
    CP_COMMIT();

    for (int it = 0; it < NCH; it++) {
        CP_WAIT1();            // chunk it arrived (this thread's groups)
        __syncthreads();       // publish chunk it; all warps done with it-1
        if (it + 2 < NCH) load_stage((it + 2) % 3, (it + 2) * 64);
        CP_COMMIT();           // keep one group per iteration

        const uint32_t ab = sb + (it % 3) * STAGE_B;
        const uint32_t bbm = ab + 16384;

        #pragma unroll
        for (int ks = 0; ks < 4; ks++) {
            const int q0 = ks * 2;
            uint32_t af[2][4];
            {
                const int qa = q0 + aqsel;
                ldsm_x4(af[0], ab + abase0 + (uint32_t)((qa ^ axor) * 16));
                ldsm_x4(af[1], ab + abase1 + (uint32_t)((qa ^ axor) * 16));
            }
            #pragma unroll
            for (int nt2 = 0; nt2 < 4; nt2++) {
                const int row = brow + nt2 * 16;
                const int qb = q0 + bqsel;
                uint32_t bf[4];
                ldsm_x4(bf, bbm + (uint32_t)row * 128 + (uint32_t)((qb ^ (row & 7)) * 16));
                mma_f16(acc[0][nt2*2  ], af[0], bf[0], bf[2]);
                mma_f16(acc[0][nt2*2+1], af[0], bf[1], bf[3]);
                mma_f16(acc[1][nt2*2  ], af[1], bf[0], bf[2]);
                mma_f16(acc[1][nt2*2+1], af[1], bf[1], bf[3]);
            }
        }
    }

    // ---------------- epilogue ----------------
    #pragma unroll
    for (int mt = 0; mt < 2; mt++) {
        #pragma unroll
        for (int idx = 0; idx < 8; idx++) {
            const int nt2 = idx >> 1, tt = idx & 1;
            const int m0 = mT + wm * 32 + mt * 16 + lq;
            const int n0 = nT + wn * 64 + nt2 * 16 + tt * 8 + (lr << 1);
            const float* cc = acc[mt][idx];

            if (MODE == 6) {
                const int bi = m0 >> 12;
                const int hw = m0 & 4095;
                __half2* dst = isq ? (__half2*)out1
                                   : ((n0 < CH) ? (__half2*)aux : (__half2*)out2);
                const int ch = n0 & (CH - 1);
                __half2* p = dst + (size_t)bi * CP2 * HWSZ + (size_t)(ch >> 1) * HWSZ;
                p[hw    ] = __floats2half2_rn(cc[0], cc[1]);
                p[hw + 8] = __floats2half2_rn(cc[2], cc[3]);
            } else if (MODE == 0) {
                float* o = (float*)out1;
                float2 bv = *(const float2*)&bias[n0];
                *(float2*)&o[(size_t)m0 * CH + n0] =
                    make_float2(cc[0] + bv.x, cc[1] + bv.y);
                *(float2*)&o[(size_t)(m0 + 8) * CH + n0] =
                    make_float2(cc[2] + bv.x, cc[3] + bv.y);
            } else if (MODE == 1) {
                __half* o = (__half*)out1;
                float2 bv = *(const float2*)&bias[n0];
                float v[4] = {cc[0] + bv.x, cc[1] + bv.y, cc[2] + bv.x, cc[3] + bv.y};
                #pragma unroll
                for (int u = 0; u < 4; u++)
                    v[u] = 0.5f * v[u] * (1.f + erff(v[u] * 0.70710678118654752f));
                *(__half2*)&o[(size_t)m0 * HID + n0]       = __floats2half2_rn(v[0], v[1]);
                *(__half2*)&o[(size_t)(m0 + 8) * HID + n0] = __floats2half2_rn(v[2], v[3]);
            } else {
                float* o = (float*)out1;
                const float* resid = (const float*)aux;
                float2 bv = *(const float2*)&bias[n0];
                float2 r0 = *(const float2*)&resid[(size_t)m0 * CH + n0];
                float2 r1 = *(const float2*)&resid[(size_t)(m0 + 8) * CH + n0];
                const int bi = m0 >> 12;
                const int hw = m0 & 4095;
                float* p = o + (size_t)bi * CH * HWSZ;
                p[(size_t)(n0    ) * HWSZ + hw    ] = cc[0] + bv.x + r0.x;
                p[(size_t)(n0 + 1) * HWSZ + hw    ] = cc[1] + bv.y + r0.y;
                p[(size_t)(n0    ) * HWSZ + hw + 8] = cc[2] + bv.x + r1.x;
                p[(size_t)(n0 + 1) * HWSZ + hw + 8] = cc[3] + bv.y + r1.y;
            }
        }
    }
}

// =====================================================================
// Tiled transpose + fp16 cvt: [b][256][4096] fp32 -> [b*4096][256] fp16
// =====================================================================
__global__ void transpose_h(const float* __restrict__ in, __half* __restrict__ out)
{
    __shared__ float t[32][33];
    const int b  = blockIdx.z;
    const int p0 = blockIdx.x * 32;
    const int c0 = blockIdx.y * 32;
    const int tx = threadIdx.x, ty = threadIdx.y;   // 32 x 8
    const float* ib = in + (size_t)b * CH * HWSZ;
    __half* ob = out + (size_t)b * HWSZ * CH;
    #pragma unroll
    for (int i = 0; i < 4; i++)
        t[ty + 8*i][tx] = ib[(size_t)(c0 + ty + 8*i) * HWSZ + p0 + tx];
    __syncthreads();
    #pragma unroll
    for (int i = 0; i < 4; i++)
        ob[(size_t)(p0 + ty + 8*i) * CH + c0 + tx] = __float2half_rn(t[tx][ty + 8*i]);
}

// =====================================================================
// Dilated 3x3 local attention (round-8 proven): branchless gathers.
// =====================================================================
__global__ __launch_bounds__(128)
void attn_kernel(const __half2* __restrict__ q,
                 const __half2* __restrict__ k,
                 const __half2* __restrict__ v,
                 __half2* __restrict__ xo)
{
    const int b    = blockIdx.z;
    const int head = blockIdx.y;
    const int n    = blockIdx.x * 128 + threadIdx.x;
    const int py   = n >> 6;
    const int px   = n & 63;
    const int dil  = (head >> 1) + 1;

    const size_t base = ((size_t)b * CP2 + head * (HDIM/2)) * HWSZ;
    const __half2* qb = q + base + n;
    const __half2* kb = k + base;
    const __half2* vb = v + base;

    float2 qr[16];
    #pragma unroll
    for (int cp = 0; cp < 16; cp++) qr[cp] = __half22float2(qb[(size_t)cp * HWSZ]);

    int nn[9];
    float msk[9];
    #pragma unroll
    for (int t = 0; t < 9; t++) {
        int yy = py + (t / 3 - 1) * dil;
        int xx = px + (t % 3 - 1) * dil;
        const bool in = (yy >= 0 && yy < HH && xx >= 0 && xx < WW);
        nn[t] = in ? (yy * WW + xx) : n;
        msk[t] = in ? 1.f : 0.f;
    }

    float logit[9];
    #pragma unroll
    for (int t = 0; t < 9; t++) {
        float acc = 0.f;
        #pragma unroll
        for (int cp = 0; cp < 16; cp++) {
            float2 kv = __half22float2(kb[(size_t)cp * HWSZ + nn[t]]);
            acc += qr[cp].x * kv.x + qr[cp].y * kv.y;
        }
        logit[t] = acc * msk[t] * 0.17677669529663687f;
    }

    float mx = logit[0];
    #pragma unroll
    for (int t = 1; t < 9; t++) mx = fmaxf(mx, logit[t]);
    float s = 0.f;
    #pragma unroll
    for (int t = 0; t < 9; t++) { logit[t] = __expf(logit[t] - mx); s += logit[t]; }
    const float inv = 1.f / s;
    #pragma unroll
    for (int t = 0; t < 9; t++) logit[t] *= inv * msk[t];

    __half2* xrow = xo + (size_t)(b * HWSZ + n) * CP2 + head * (HDIM/2);
    #pragma unroll
    for (int cp = 0; cp < 16; cp++) {
        float ox = 0.f, oy = 0.f;
        #pragma unroll
        for (int t = 0; t < 9; t++) {
            float2 vv = __half22float2(vb[(size_t)cp * HWSZ + nn[t]]);
            ox += logit[t] * vv.x;
            oy += logit[t] * vv.y;
        }
        xrow[cp] = __floats2half2_rn(ox, oy);
    }
}

// =====================================================================
// LayerNorm over 256 channels: fp32 in (g_xp), fp16 out (g_ln).
// =====================================================================
__global__ void ln_kernel(const float* __restrict__ xp,
                          const float* __restrict__ w,
                          const float* __restrict__ bb,
                          __half2* __restrict__ out)
{
    const int warp = threadIdx.x >> 5;
    const int lane = threadIdx.x & 31;
    const int tok  = blockIdx.x * 8 + warp;
    const float* row = xp + (size_t)tok * CH;

    float4 v0 = *(const float4*)&row[lane * 8];
    float4 v1 = *(const float4*)&row[lane * 8 + 4];
    float va[8] = {v0.x, v0.y, v0.z, v0.w, v1.x, v1.y, v1.z, v1.w};

    float s = 0.f, sq = 0.f;
    #pragma unroll
    for (int u = 0; u < 8; u++) { s += va[u]; sq += va[u] * va[u]; }
    #pragma unroll
    for (int o = 16; o; o >>= 1) {
        s  += __shfl_xor_sync(0xffffffffu, s,  o);
        sq += __shfl_xor_sync(0xffffffffu, sq, o);
    }
    const float mean = s * (1.f / 256.f);
    const float var  = sq * (1.f / 256.f) - mean * mean;
    const float inv  = rsqrtf(var + 1e-5f);

    __half2* orow = out + (size_t)tok * CP2 + lane * 4;
    #pragma unroll
    for (int j = 0; j < 4; j++) {
        int ch = lane * 8 + j * 2;
        float a0 = (va[j*2]   - mean) * inv * w[ch]     + bb[ch];
        float a1 = (va[j*2+1] - mean) * inv * w[ch + 1] + bb[ch + 1];
        orow[j] = __floats2half2_rn(a0, a1);
    }
}

// =====================================================================
// Fused weight conversion: all six weights in one launch.
// =====================================================================
__global__ void cvt_all(const float* __restrict__ wq, const float* __restrict__ wk,
                        const float* __restrict__ wv, const float* __restrict__ wp,
                        const float* __restrict__ w1, const float* __restrict__ w2,
                        __half* __restrict__ owq, __half* __restrict__ owkv,
                        __half* __restrict__ owp, __half* __restrict__ ow1,
                        __half* __restrict__ ow2)
{
    const int i = blockIdx.x * 256 + threadIdx.x;
    const int S = CH * CH;          // 65536
    if      (i <     S) owq [i        ] = __float2half_rn(wq[i]);
    else if (i < 2 * S) owkv[i - S    ] = __float2half_rn(wk[i - S]);
    else if (i < 3 * S) owkv[i - S    ] = __float2half_rn(wv[i - 2*S]);
    else if (i < 4 * S) owp [i - 3*S  ] = __float2half_rn(wp[i - 3*S]);
    else if (i < 8 * S) ow1 [i - 4*S  ] = __float2half_rn(w1[i - 4*S]);
    else                ow2 [i - 8*S  ] = __float2half_rn(w2[i - 8*S]);
}

// =====================================================================
extern "C" void kernel_launch(void* const* d_in, const int* in_sizes, int n_in,
                              void* d_out, int out_size)
{
    const float* sub    = (const float*)d_in[0];
    const float* ori    = (const float*)d_in[1];
    const float* wq     = (const float*)d_in[2];
    const float* wk     = (const float*)d_in[3];
    const float* wv     = (const float*)d_in[4];
    const float* proj_w = (const float*)d_in[5];
    const float* proj_b = (const float*)d_in[6];
    const float* ln_w   = (const float*)d_in[7];
    const float* ln_b   = (const float*)d_in[8];
    const float* fc1_w  = (const float*)d_in[9];
    const float* fc1_b  = (const float*)d_in[10];
    const float* fc2_w  = (const float*)d_in[11];
    const float* fc2_b  = (const float*)d_in[12];
    float* out = (float*)d_out;

    __half *p_ts, *p_to, *p_ln, *p_h, *p_wq, *p_wkv, *p_wp, *p_w1, *p_w2;
    __half2 *p_q, *p_k, *p_v, *p_x;
    float *p_xp;
    cudaGetSymbolAddress((void**)&p_ts,  g_ts);
    cudaGetSymbolAddress((void**)&p_to,  g_to);
    cudaGetSymbolAddress((void**)&p_q,   g_q);
    cudaGetSymbolAddress((void**)&p_k,   g_k);
    cudaGetSymbolAddress((void**)&p_v,   g_v);
    cudaGetSymbolAddress((void**)&p_x,   g_x);
    cudaGetSymbolAddress((void**)&p_xp,  g_xp);
    cudaGetSymbolAddress((void**)&p_ln,  g_ln);
    cudaGetSymbolAddress((void**)&p_h,   g_h);
    cudaGetSymbolAddress((void**)&p_wq,  g_wq);
    cudaGetSymbolAddress((void**)&p_wkv, g_wkv);
    cudaGetSymbolAddress((void**)&p_wp,  g_wp);
    cudaGetSymbolAddress((void**)&p_w1,  g_w1);
    cudaGetSymbolAddress((void**)&p_w2,  g_w2);

    cudaFuncSetAttribute(gemm_h<6, CH >, cudaFuncAttributeMaxDynamicSharedMemorySize, SMEM_SZ);
    cudaFuncSetAttribute(gemm_h<0, CH >, cudaFuncAttributeMaxDynamicSharedMemorySize, SMEM_SZ);
    cudaFuncSetAttribute(gemm_h<1, CH >, cudaFuncAttributeMaxDynamicSharedMemorySize, SMEM_SZ);
    cudaFuncSetAttribute(gemm_h<2, HID>, cudaFuncAttributeMaxDynamicSharedMemorySize, SMEM_SZ);

    // 0: all weight conversions
    cvt_all<<<(12 * CH * CH) / 256, 256>>>(wq, wk, wv, proj_w, fc1_w, fc2_w,
                                           p_wq, p_wkv, p_wp, p_w1, p_w2);

    // 1,2: transpose inputs to [tok][c] fp16
    dim3 gt(HWSZ / 32, CH / 32, BATCH);
    dim3 bt(32, 8);
    transpose_h<<<gt, bt>>>(sub, p_ts);
    transpose_h<<<gt, bt>>>(ori, p_to);

    // 3: combined q + kv GEMM (bx<2: q; bx>=2: k|v)
    dim3 gqkv(6, NTOK / 128);
    gemm_h<6, CH><<<gqkv, 256, SMEM_SZ>>>(p_ts, p_wq, nullptr, p_q, p_k,
                                          p_to, p_wkv, p_v);

    // 4: attention -> g_x [tok][c] fp16
    dim3 ga(HWSZ / 128, NHEAD, BATCH);
    attn_kernel<<<ga, 128>>>(p_q, p_k, p_v, p_x);

    // 5: proj + bias -> g_xp fp32
    dim3 gp(CH / 128, NTOK / 128);
    gemm_h<0, CH><<<gp, 256, SMEM_SZ>>>((const __half*)p_x, p_wp, proj_b, p_xp,
                                        nullptr, nullptr, nullptr, nullptr);

    // 6: layernorm -> g_ln fp16
    ln_kernel<<<NTOK / 8, 256>>>(p_xp, ln_w, ln_b, (__half2*)p_ln);

    // 7: fc1 + bias + GELU -> g_h fp16
    dim3 g1(HID / 128, NTOK / 128);
    gemm_h<1, CH><<<g1, 256, SMEM_SZ>>>(p_ln, p_w1, fc1_b, p_h,
                                        nullptr, nullptr, nullptr, nullptr);

    // 8: fc2 + bias + residual, transposed fp32 store -> d_out [B][C][H][W]
    dim3 g2(CH / 128, NTOK / 128);
    gemm_h<2, HID><<<g2, 256, SMEM_SZ>>>(p_h, p_w2, fc2_b, out, p_xp,
                                         nullptr, nullptr, nullptr);
}